// round 15
// baseline (speedup 1.0000x reference)
#include <cuda_runtime.h>
#include <math.h>

#define BB 8
#define CC 64
#define NN 4096
#define TILE_N 128
#define NTB (NN/TILE_N)      // 32 n-tiles per batch
#define TILES (BB*NTB)       // 256 blocks, 2 CTAs/SM, all co-resident
#define NTHR 256

typedef unsigned long long u64;

// Scratch (allocation-free: __device__ globals)
__device__ float g_psum[BB*CC*NTB];        // partial Σz   [b][o][nb]
__device__ float g_psq [BB*CC*NTB];        // partial Σz²  [b][o][nb]
__device__ float g_spart[TILES];           // partial s_b  [b][nb]
__device__ unsigned int g_bar = 0;         // monotonic grid barrier

// ---- f32x2 packed helpers (sm_103a) ----
__device__ __forceinline__ u64 ffma2(u64 a, u64 b, u64 c) {
    u64 d;
    asm("fma.rn.f32x2 %0, %1, %2, %3;" : "=l"(d) : "l"(a), "l"(b), "l"(c));
    return d;
}
__device__ __forceinline__ u64 packdup(float v) {
    u64 r;
    asm("mov.b64 %0, {%1, %2};" : "=l"(r) : "f"(v), "f"(v));
    return r;
}
__device__ __forceinline__ void unpack2(u64 v, float& lo, float& hi) {
    asm("mov.b64 {%0, %1}, %2;" : "=f"(lo), "=f"(hi) : "l"(v));
}

// Replay-safe grid barrier (single round per launch).
__device__ __forceinline__ void grid_barrier() {
    __syncthreads();
    if (threadIdx.x == 0) {
        unsigned int old;
        asm volatile("atom.release.gpu.global.add.u32 %0, [%1], 1;"
                     : "=r"(old) : "l"(&g_bar) : "memory");
        unsigned int target = (old / TILES + 1u) * TILES;
        unsigned int v;
        do {
            asm volatile("ld.acquire.gpu.u32 %0, [%1];" : "=r"(v) : "l"(&g_bar));
        } while ((int)(v - target) < 0);
    }
    __syncthreads();
}

// ============================================================================
// Fused: GEMM (64o × 128n tile, 256 threads / 8 warps, warp-per-8o,
// software-pipelined) -> stats partials -> grid barrier -> redundant
// finalize -> epilogue from registers.  2 CTAs/SM for prologue/epilogue
// overlap and full-chip coverage.
// ============================================================================
__global__ __launch_bounds__(NTHR, 2)
void fused(const float* __restrict__ x,
           const float* __restrict__ wvec,
           const float* __restrict__ W,
           const float* __restrict__ conv_b,
           const float* __restrict__ gamma,
           const float* __restrict__ beta,
           float* __restrict__ out)
{
    extern __shared__ char sm[];
    u64*   wt2 = (u64*)sm;                  // [64][64] dup pairs (32 KB)
    float* xs  = (float*)(sm + 32768);      // [64][128]           (32 KB)
    // post-barrier reuse of the xs region:
    float* zZ    = xs;                      // [512]
    float* zQ    = xs + 512;                // [512]
    float* sc_sh = xs + 1024;               // [64]
    float* bi_sh = xs + 1088;               // [64]
    float* s_sh  = xs + 1152;               // [8]
    __shared__ float sred[4];

    const int t    = threadIdx.x;
    const int tile = blockIdx.x;
    const int b    = tile >> 5;
    const int nb   = tile & 31;
    const int n0   = nb * TILE_N;

    // ---- x tile: direct LDG -> STS, 2048 float4, 8 per thread ----
    const float4* x4 = (const float4*)(x + ((size_t)b * CC) * NN + n0);
    #pragma unroll
    for (int i = 0; i < 8; i++) {
        int idx = i * NTHR + t;
        int c = idx >> 5, j = idx & 31;
        ((float4*)(xs + c * TILE_N))[j] = x4[c * (NN / 4) + j];
    }

    // ---- tanh(w)² partial for this 128-wide n-slice (warps 0-3) ----
    if (t < 128) {
        float vv = tanhf(wvec[b * NN + n0 + t]);
        vv = fmaxf(vv, 0.f);
        float sp = vv * vv;
        #pragma unroll
        for (int off = 16; off > 0; off >>= 1)
            sp += __shfl_xor_sync(0xFFFFFFFFu, sp, off);
        if ((t & 31) == 0) sred[t >> 5] = sp;
    }

    // ---- W dup-packed (transposed): wt2[c][o] = {W[o,c], W[o,c]} ----
    #pragma unroll
    for (int i = 0; i < 16; i++) {
        int idx = i * NTHR + t;
        wt2[(idx & 63) * 64 + (idx >> 6)] = packdup(W[idx]);
    }
    __syncthreads();
    if (t == 0) g_spart[tile] = (sred[0] + sred[1]) + (sred[2] + sred[3]);

    const int wid = t >> 5, lane = t & 31;   // wid 0..7
    const int o0 = wid * 8;                  // 8 o's per warp
    const float* xA = xs + lane * 4;         // conflict-free (banks 4l..4l+3)
    const u64*   wp = wt2 + o0;

    u64 acc[8][2];
    #pragma unroll
    for (int i = 0; i < 8; i++) { acc[i][0] = 0ull; acc[i][1] = 0ull; }

    // ---- software-pipelined c-loop ----
    ulonglong2 cw01 = *(const ulonglong2*)(wp);
    ulonglong2 cw23 = *(const ulonglong2*)(wp + 2);
    ulonglong2 cw45 = *(const ulonglong2*)(wp + 4);
    ulonglong2 cw67 = *(const ulonglong2*)(wp + 6);
    ulonglong2 cxa  = *(const ulonglong2*)(xA);

    #pragma unroll 7
    for (int c = 0; c < 63; c++) {
        ulonglong2 nw01 = *(const ulonglong2*)(wp + (c + 1) * 64);
        ulonglong2 nw23 = *(const ulonglong2*)(wp + (c + 1) * 64 + 2);
        ulonglong2 nw45 = *(const ulonglong2*)(wp + (c + 1) * 64 + 4);
        ulonglong2 nw67 = *(const ulonglong2*)(wp + (c + 1) * 64 + 6);
        ulonglong2 nxa  = *(const ulonglong2*)(xA + (c + 1) * TILE_N);

        acc[0][0] = ffma2(cw01.x, cxa.x, acc[0][0]);
        acc[0][1] = ffma2(cw01.x, cxa.y, acc[0][1]);
        acc[1][0] = ffma2(cw01.y, cxa.x, acc[1][0]);
        acc[1][1] = ffma2(cw01.y, cxa.y, acc[1][1]);
        acc[2][0] = ffma2(cw23.x, cxa.x, acc[2][0]);
        acc[2][1] = ffma2(cw23.x, cxa.y, acc[2][1]);
        acc[3][0] = ffma2(cw23.y, cxa.x, acc[3][0]);
        acc[3][1] = ffma2(cw23.y, cxa.y, acc[3][1]);
        acc[4][0] = ffma2(cw45.x, cxa.x, acc[4][0]);
        acc[4][1] = ffma2(cw45.x, cxa.y, acc[4][1]);
        acc[5][0] = ffma2(cw45.y, cxa.x, acc[5][0]);
        acc[5][1] = ffma2(cw45.y, cxa.y, acc[5][1]);
        acc[6][0] = ffma2(cw67.x, cxa.x, acc[6][0]);
        acc[6][1] = ffma2(cw67.x, cxa.y, acc[6][1]);
        acc[7][0] = ffma2(cw67.y, cxa.x, acc[7][0]);
        acc[7][1] = ffma2(cw67.y, cxa.y, acc[7][1]);

        cw01 = nw01; cw23 = nw23; cw45 = nw45; cw67 = nw67; cxa = nxa;
    }
    // final iteration (c = 63)
    acc[0][0] = ffma2(cw01.x, cxa.x, acc[0][0]);
    acc[0][1] = ffma2(cw01.x, cxa.y, acc[0][1]);
    acc[1][0] = ffma2(cw01.y, cxa.x, acc[1][0]);
    acc[1][1] = ffma2(cw01.y, cxa.y, acc[1][1]);
    acc[2][0] = ffma2(cw23.x, cxa.x, acc[2][0]);
    acc[2][1] = ffma2(cw23.x, cxa.y, acc[2][1]);
    acc[3][0] = ffma2(cw23.y, cxa.x, acc[3][0]);
    acc[3][1] = ffma2(cw23.y, cxa.y, acc[3][1]);
    acc[4][0] = ffma2(cw45.x, cxa.x, acc[4][0]);
    acc[4][1] = ffma2(cw45.x, cxa.y, acc[4][1]);
    acc[5][0] = ffma2(cw45.y, cxa.x, acc[5][0]);
    acc[5][1] = ffma2(cw45.y, cxa.y, acc[5][1]);
    acc[6][0] = ffma2(cw67.x, cxa.x, acc[6][0]);
    acc[6][1] = ffma2(cw67.x, cxa.y, acc[6][1]);
    acc[7][0] = ffma2(cw67.y, cxa.x, acc[7][0]);
    acc[7][1] = ffma2(cw67.y, cxa.y, acc[7][1]);

    // ---- per-o stats partials ----
    #pragma unroll
    for (int i = 0; i < 8; i++) {
        float v0, v1, v2, v3;
        unpack2(acc[i][0], v0, v1);
        unpack2(acc[i][1], v2, v3);
        float s = (v0 + v1) + (v2 + v3);
        float q = fmaf(v0, v0, fmaf(v1, v1, fmaf(v2, v2, v3 * v3)));
        #pragma unroll
        for (int off = 16; off > 0; off >>= 1) {
            s += __shfl_xor_sync(0xFFFFFFFFu, s, off);
            q += __shfl_xor_sync(0xFFFFFFFFu, q, off);
        }
        if (lane == 0) {
            g_psum[(b * CC + (o0 + i)) * NTB + nb] = s;
            g_psq [(b * CC + (o0 + i)) * NTB + nb] = q;
        }
    }

    // ---- publish + grid barrier ----
    __threadfence();
    grid_barrier();

    // ---- redundant finalize (every block; partials are L2-resident) ----
    {   // s_b: warp wid reduces batch wid's 32 tile partials (8 warps = 8 b)
        float sp = g_spart[wid * NTB + lane];
        #pragma unroll
        for (int off = 16; off > 0; off >>= 1)
            sp += __shfl_xor_sync(0xFFFFFFFFu, sp, off);
        if (lane == 0) s_sh[wid] = sp;
    }
    #pragma unroll
    for (int k = 0; k < 2; k++) {   // Z,Q: thread does rows t and t+256
        int bo = t + k * 256;
        const float4* p4 = (const float4*)(g_psum + bo * NTB);
        const float4* q4 = (const float4*)(g_psq  + bo * NTB);
        float Z = 0.f, Q = 0.f;
        #pragma unroll
        for (int i = 0; i < NTB / 4; i++) {
            float4 a = p4[i], c = q4[i];
            Z += (a.x + a.y) + (a.z + a.w);
            Q += (c.x + c.y) + (c.z + c.w);
        }
        zZ[bo] = Z; zQ[bo] = Q;
    }
    __syncthreads();

    if (t < CC) {        // per-o closed-form BN -> scale/bias for batch b
        const int o = t;
        float cb = conv_b[o];
        float alpha_b = 0.f, off_b = 0.f;
        float mean_acc = 0.f, sq_acc = 0.f;
        #pragma unroll
        for (int bb = 0; bb < BB; bb++) {
            float s = s_sh[bb];
            float a = 1.f / (1.f + (float)NN * s);
            float Z = zZ[bb * CC + o];
            float Q = zQ[bb * CC + o];
            float off = a * s * Z + cb;
            if (bb == b) { alpha_b = a; off_b = off; }
            mean_acc += a * Z + (float)NN * off;
            sq_acc   += a * a * Q + 2.f * a * off * Z + (float)NN * off * off;
        }
        const float inv_cnt = 1.f / (float)(BB * NN);
        float mean = mean_acc * inv_cnt;
        float var  = sq_acc * inv_cnt - mean * mean;
        float invstd = rsqrtf(var + 1e-5f);
        float g = gamma[o] * invstd;
        sc_sh[o] = alpha_b * g;
        bi_sh[o] = (off_b - mean) * g + beta[o];
    }
    __syncthreads();

    // ---- epilogue straight from registers ----
    #pragma unroll
    for (int i = 0; i < 8; i++) {
        const int o = o0 + i;
        const float sc = sc_sh[o];
        const float bi = bi_sh[o];
        float v0, v1, v2, v3;
        unpack2(acc[i][0], v0, v1);
        unpack2(acc[i][1], v2, v3);
        float4 r;
        r.x = fmaxf(fmaf(sc, v0, bi), 0.f);
        r.y = fmaxf(fmaf(sc, v1, bi), 0.f);
        r.z = fmaxf(fmaf(sc, v2, bi), 0.f);
        r.w = fmaxf(fmaf(sc, v3, bi), 0.f);
        *(float4*)(out + ((size_t)(b * CC + o)) * NN + n0 + lane * 4) = r;
    }
}

extern "C" void kernel_launch(void* const* d_in, const int* in_sizes, int n_in,
                              void* d_out, int out_size) {
    const float* x      = (const float*)d_in[0];  // [8,64,4096,1]
    const float* w      = (const float*)d_in[1];  // [8,4096]
    const float* conv_w = (const float*)d_in[2];  // [64,64,1,1]
    const float* conv_b = (const float*)d_in[3];  // [64]
    const float* gamma  = (const float*)d_in[4];  // [64]
    const float* beta   = (const float*)d_in[5];  // [64]
    float* out = (float*)d_out;

    cudaFuncSetAttribute(fused,
                         cudaFuncAttributeMaxDynamicSharedMemorySize, 65536);
    fused<<<TILES, NTHR, 65536>>>(x, w, conv_w, conv_b, gamma, beta, out);
}

// round 17
// speedup vs baseline: 1.7287x; 1.7287x over previous
#include <cuda_runtime.h>
#include <math.h>

#define BB 8
#define CC 64
#define NN 4096
#define TILE_N 256
#define NTB 16               // n-tiles per batch
#define TILES 128            // grid; 1 CTA/SM, co-resident
#define NTHR 256
#define XSTR 264             // padded row stride (words) for xh/xl

typedef unsigned long long u64;
typedef unsigned int u32;

// ---- dynamic smem layout (bytes) ----
#define OFF_AH   0           // W hi, fragment-major: 4096 words (16384 B)
#define OFF_AL   16384
#define OFF_XH   32768       // x hi: 64 rows * 264 words = 67584 B
#define OFF_XL   100352
#define OFF_PS   167936      // float ps[8][64]
#define OFF_PQ   169984
#define OFF_ZZ   172032      // float zZ[512]
#define OFF_ZQ   174080
#define OFF_SC   176128      // float sc[64]
#define OFF_BI   176384
#define OFF_SS   176640      // float s_sh[8]
#define OFF_SRED 176704      // float sred[8]
#define SMEM_TOTAL 176768

// Scratch (allocation-free: __device__ globals)
__device__ float g_psum[BB*CC*NTB];        // partial Σz   [b][o][nb]
__device__ float g_psq [BB*CC*NTB];        // partial Σz²  [b][o][nb]
__device__ float g_spart[TILES];           // partial s_b  [b][nb]
__device__ unsigned int g_bar = 0;         // monotonic grid barrier

__device__ __forceinline__ u32 f2tf(float v) {
    u32 r; asm("cvt.rna.tf32.f32 %0, %1;" : "=r"(r) : "f"(v)); return r;
}
__device__ __forceinline__ void mma_tf32(float* d, const u32* a, u32 b0, u32 b1) {
    asm volatile(
        "mma.sync.aligned.m16n8k8.row.col.f32.tf32.tf32.f32 "
        "{%0,%1,%2,%3}, {%4,%5,%6,%7}, {%8,%9}, {%0,%1,%2,%3};"
        : "+f"(d[0]), "+f"(d[1]), "+f"(d[2]), "+f"(d[3])
        : "r"(a[0]), "r"(a[1]), "r"(a[2]), "r"(a[3]), "r"(b0), "r"(b1));
}

// Replay-safe grid barrier (single round per launch).
__device__ __forceinline__ void grid_barrier() {
    __syncthreads();
    if (threadIdx.x == 0) {
        unsigned int old;
        asm volatile("atom.release.gpu.global.add.u32 %0, [%1], 1;"
                     : "=r"(old) : "l"(&g_bar) : "memory");
        unsigned int target = (old / TILES + 1u) * TILES;
        unsigned int v;
        do {
            asm volatile("ld.acquire.gpu.u32 %0, [%1];" : "=r"(v) : "l"(&g_bar));
        } while ((int)(v - target) < 0);
    }
    __syncthreads();
}

// ============================================================================
// Fused 3xTF32 tensor-core kernel. Per 256n tile: z[64o][256n] = W·x via
// mma.sync.m16n8k8 (hi·hi + lo·hi + hi·lo), stats from fragments, grid
// barrier, redundant finalize, epilogue from fragments. Single launch.
// ============================================================================
__global__ __launch_bounds__(NTHR, 1)
void fused(const float* __restrict__ x,
           const float* __restrict__ wvec,
           const float* __restrict__ W,
           const float* __restrict__ conv_b,
           const float* __restrict__ gamma,
           const float* __restrict__ beta,
           float* __restrict__ out)
{
    extern __shared__ char sm[];
    u32*   AhS  = (u32*)(sm + OFF_AH);
    u32*   AlS  = (u32*)(sm + OFF_AL);
    u32*   XH   = (u32*)(sm + OFF_XH);
    u32*   XL   = (u32*)(sm + OFF_XL);
    float* ps   = (float*)(sm + OFF_PS);
    float* pq   = (float*)(sm + OFF_PQ);
    float* zZ   = (float*)(sm + OFF_ZZ);
    float* zQ   = (float*)(sm + OFF_ZQ);
    float* sc_sh= (float*)(sm + OFF_SC);
    float* bi_sh= (float*)(sm + OFF_BI);
    float* s_sh = (float*)(sm + OFF_SS);
    float* sred = (float*)(sm + OFF_SRED);

    const int t    = threadIdx.x;
    const int wid  = t >> 5, lane = t & 31;
    const int gid  = lane >> 2, tig = lane & 3;
    const int tile = blockIdx.x;
    const int b    = tile >> 4;
    const int nb   = tile & 15;
    const int n0   = nb * TILE_N;

    // ---- x tile: load fp32, split to tf32 hi/lo, store [c][n] padded ----
    const float4* x4 = (const float4*)(x + ((size_t)b * CC) * NN + n0);
    #pragma unroll
    for (int i = 0; i < 16; i++) {
        int idx = i * NTHR + t;
        int c = idx >> 6, j4 = idx & 63;
        float4 v = x4[c * (NN / 4) + j4];
        u32 h0 = f2tf(v.x), h1 = f2tf(v.y), h2 = f2tf(v.z), h3 = f2tf(v.w);
        u32 l0 = f2tf(v.x - __uint_as_float(h0));
        u32 l1 = f2tf(v.y - __uint_as_float(h1));
        u32 l2 = f2tf(v.z - __uint_as_float(h2));
        u32 l3 = f2tf(v.w - __uint_as_float(h3));
        *(uint4*)(XH + c * XSTR + j4 * 4) = make_uint4(h0, h1, h2, h3);
        *(uint4*)(XL + c * XSTR + j4 * 4) = make_uint4(l0, l1, l2, l3);
    }

    // ---- tanh(w)² partial for this 256-wide n-slice ----
    {
        float vv = tanhf(wvec[b * NN + n0 + t]);
        vv = fmaxf(vv, 0.f);
        float sp = vv * vv;
        #pragma unroll
        for (int off = 16; off > 0; off >>= 1)
            sp += __shfl_xor_sync(0xFFFFFFFFu, sp, off);
        if (lane == 0) sred[wid] = sp;
    }

    // ---- W -> fragment-major A tiles (hi/lo) ----
    // word(tile kt,mt) = (kt*4+mt)*128 + (g*4+tg)*4 + (h8 + 2*ch)
    #pragma unroll
    for (int i = 0; i < 16; i++) {
        int idx = i * NTHR + t;
        int o = idx >> 6, c = idx & 63;
        float v = W[idx];
        u32 hb = f2tf(v);
        u32 lb = f2tf(v - __uint_as_float(hb));
        int mt = o >> 4, r = o & 15;
        int g_ = r & 7, h8 = r >> 3;
        int kt = c >> 3, cc = c & 7;
        int tg = cc & 3, ch = cc >> 2;
        int word = (kt * 4 + mt) * 128 + (g_ * 4 + tg) * 4 + (h8 + 2 * ch);
        AhS[word] = hb;
        AlS[word] = lb;
    }
    __syncthreads();
    if (t == 0) {
        float s = 0.f;
        #pragma unroll
        for (int i = 0; i < 8; i++) s += sred[i];
        g_spart[tile] = s;
    }

    // ---- MMA mainloop: warp owns all 4 m-tiles × its 4 n-tiles ----
    float acc[4][4][4];
    #pragma unroll
    for (int mt = 0; mt < 4; mt++)
        #pragma unroll
        for (int ntl = 0; ntl < 4; ntl++)
            #pragma unroll
            for (int j = 0; j < 4; j++) acc[mt][ntl][j] = 0.f;

    #pragma unroll
    for (int kt = 0; kt < 8; kt++) {
        u32 ah[4][4], al[4][4];
        #pragma unroll
        for (int mt = 0; mt < 4; mt++) {
            *(uint4*)ah[mt] = *(const uint4*)(AhS + (kt * 4 + mt) * 128 + lane * 4);
            *(uint4*)al[mt] = *(const uint4*)(AlS + (kt * 4 + mt) * 128 + lane * 4);
        }
        const int r0 = (kt * 8 + tig) * XSTR;
        const int r1 = (kt * 8 + tig + 4) * XSTR;
        #pragma unroll
        for (int ntl = 0; ntl < 4; ntl++) {
            int nn = wid * 32 + ntl * 8 + gid;
            u32 bh0 = XH[r0 + nn], bh1 = XH[r1 + nn];
            u32 bl0 = XL[r0 + nn], bl1 = XL[r1 + nn];
            #pragma unroll
            for (int mt = 0; mt < 4; mt++) {
                mma_tf32(acc[mt][ntl], ah[mt], bh0, bh1);
                mma_tf32(acc[mt][ntl], al[mt], bh0, bh1);
                mma_tf32(acc[mt][ntl], ah[mt], bl0, bl1);
            }
        }
    }

    // ---- stats from fragments: rows o = mt*16+gid and +8; cols = n ----
    #pragma unroll
    for (int mt = 0; mt < 4; mt++) {
        float s0 = 0.f, q0 = 0.f, s1 = 0.f, q1 = 0.f;
        #pragma unroll
        for (int ntl = 0; ntl < 4; ntl++) {
            float c0 = acc[mt][ntl][0], c1 = acc[mt][ntl][1];
            float c2 = acc[mt][ntl][2], c3 = acc[mt][ntl][3];
            s0 += c0 + c1; q0 += c0 * c0 + c1 * c1;
            s1 += c2 + c3; q1 += c2 * c2 + c3 * c3;
        }
        #pragma unroll
        for (int off = 1; off <= 2; off <<= 1) {   // reduce over tig lanes
            s0 += __shfl_xor_sync(0xFFFFFFFFu, s0, off);
            q0 += __shfl_xor_sync(0xFFFFFFFFu, q0, off);
            s1 += __shfl_xor_sync(0xFFFFFFFFu, s1, off);
            q1 += __shfl_xor_sync(0xFFFFFFFFu, q1, off);
        }
        if (tig == 0) {
            ps[wid * 64 + mt * 16 + gid]     = s0;
            pq[wid * 64 + mt * 16 + gid]     = q0;
            ps[wid * 64 + mt * 16 + 8 + gid] = s1;
            pq[wid * 64 + mt * 16 + 8 + gid] = q1;
        }
    }
    __syncthreads();
    if (t < CC) {
        float S = 0.f, Q = 0.f;
        #pragma unroll
        for (int w2 = 0; w2 < 8; w2++) { S += ps[w2 * 64 + t]; Q += pq[w2 * 64 + t]; }
        g_psum[(b * CC + t) * NTB + nb] = S;
        g_psq [(b * CC + t) * NTB + nb] = Q;
    }

    // ---- publish + grid barrier ----
    __threadfence();
    grid_barrier();

    // ---- redundant finalize (every block; partials L2-resident) ----
    {   // s_b: warp wid (0-7) reduces batch wid's 16 tile partials
        float sp = (lane < NTB) ? g_spart[wid * NTB + lane] : 0.f;
        #pragma unroll
        for (int off = 8; off > 0; off >>= 1)
            sp += __shfl_xor_sync(0xFFFFFFFFu, sp, off);
        if (lane == 0) s_sh[wid] = sp;
    }
    #pragma unroll
    for (int k = 0; k < 2; k++) {   // Z,Q rows t and t+256
        int bo = t + k * 256;
        const float4* p4 = (const float4*)(g_psum + bo * NTB);
        const float4* q4 = (const float4*)(g_psq  + bo * NTB);
        float Z = 0.f, Q = 0.f;
        #pragma unroll
        for (int i = 0; i < NTB / 4; i++) {
            float4 a = p4[i], c = q4[i];
            Z += (a.x + a.y) + (a.z + a.w);
            Q += (c.x + c.y) + (c.z + c.w);
        }
        zZ[bo] = Z; zQ[bo] = Q;
    }
    __syncthreads();

    if (t < CC) {        // per-o closed-form BN -> scale/bias for batch b
        const int o = t;
        float cb = conv_b[o];
        float alpha_b = 0.f, off_b = 0.f;
        float mean_acc = 0.f, sq_acc = 0.f;
        #pragma unroll
        for (int bb = 0; bb < BB; bb++) {
            float s = s_sh[bb];
            float a = 1.f / (1.f + (float)NN * s);
            float Z = zZ[bb * CC + o];
            float Q = zQ[bb * CC + o];
            float off = a * s * Z + cb;
            if (bb == b) { alpha_b = a; off_b = off; }
            mean_acc += a * Z + (float)NN * off;
            sq_acc   += a * a * Q + 2.f * a * off * Z + (float)NN * off * off;
        }
        const float inv_cnt = 1.f / (float)(BB * NN);
        float mean = mean_acc * inv_cnt;
        float var  = sq_acc * inv_cnt - mean * mean;
        float invstd = rsqrtf(var + 1e-5f);
        float g = gamma[o] * invstd;
        sc_sh[o] = alpha_b * g;
        bi_sh[o] = (off_b - mean) * g + beta[o];
    }
    __syncthreads();

    // ---- epilogue straight from fragments ----
    #pragma unroll
    for (int mt = 0; mt < 4; mt++) {
        const int o1 = mt * 16 + gid, o2 = o1 + 8;
        const float sa = sc_sh[o1], ba = bi_sh[o1];
        const float sb = sc_sh[o2], bbv = bi_sh[o2];
        #pragma unroll
        for (int ntl = 0; ntl < 4; ntl++) {
            int n = n0 + wid * 32 + ntl * 8 + tig * 2;
            float2 va, vb;
            va.x = fmaxf(fmaf(sa, acc[mt][ntl][0], ba), 0.f);
            va.y = fmaxf(fmaf(sa, acc[mt][ntl][1], ba), 0.f);
            vb.x = fmaxf(fmaf(sb, acc[mt][ntl][2], bbv), 0.f);
            vb.y = fmaxf(fmaf(sb, acc[mt][ntl][3], bbv), 0.f);
            *(float2*)(out + ((size_t)(b * CC + o1)) * NN + n) = va;
            *(float2*)(out + ((size_t)(b * CC + o2)) * NN + n) = vb;
        }
    }
}

extern "C" void kernel_launch(void* const* d_in, const int* in_sizes, int n_in,
                              void* d_out, int out_size) {
    const float* x      = (const float*)d_in[0];  // [8,64,4096,1]
    const float* w      = (const float*)d_in[1];  // [8,4096]
    const float* conv_w = (const float*)d_in[2];  // [64,64,1,1]
    const float* conv_b = (const float*)d_in[3];  // [64]
    const float* gamma  = (const float*)d_in[4];  // [64]
    const float* beta   = (const float*)d_in[5];  // [64]
    float* out = (float*)d_out;

    cudaFuncSetAttribute(fused,
                         cudaFuncAttributeMaxDynamicSharedMemorySize, SMEM_TOTAL);
    fused<<<TILES, NTHR, SMEM_TOTAL>>>(x, w, conv_w, conv_b, gamma, beta, out);
}